// round 15
// baseline (speedup 1.0000x reference)
#include <cuda_runtime.h>
#include <cuda_bf16.h>

// TransientCombNoise: B=32, T=2000, BLOCK=64, MAX_DELAY=480, SR=16000.
// Per row r of N=64000, params (p0..p3):
//   att   = max(16000*(0.0005 + p0*0.0495), 1)   (>= 8)
//   energy= p1 ; tilt = 2*p2 - 1
//   delay = int(64*(0.5 + 0.5*(0.05 + 0.95*p3)))  in [33, 63]
//   y[i]  = env(i)*energy*( n[i] + tilt*exp(delay/att)*n[i-delay] )
//   out   = y * rsqrt(mean(y^2) + 1e-5)
//
// Split-chunk (R14 winner) x ILP-2: 8 lanes per row; lane owns elements
// [4l,4l+3] (lo, NEVER tapped since delay>=33) and [4l+32,4l+35] (hi, the only
// tapped chunk). Each thread carries TWO independent rows (r, r+32000):
// 6 front-batched LDG.128 (params first - they head the longest dep chain
// params->delay->tap loads). Grid 1000 blocks, 6 blocks/SM -> 1.13 waves
// (vs 2.0 quantized before).

#define N_ROWS 64000
#define HALF   (N_ROWS / 2)
#define LOG2E  1.4426950408889634f

__device__ __forceinline__ void row_split(
    const float4 p, const float4 nlo, const float4 nhi,
    const float* __restrict__ noise, int row, int i0,
    float* y, float* z, float& ss)
{
    // Strict-rounded chain so the truncated delay matches JAX fp32 exactly.
    const float att    = fmaxf(__fmul_rn(16000.0f,
                         __fadd_rn(0.0005f, __fmul_rn(p.x, 0.0495f))), 1.0f);
    const float energy = p.y;
    const float tilt   = __fmaf_rn(p.z, 2.0f, -1.0f);
    const float bw     = __fadd_rn(0.05f, __fmul_rn(p.w, 0.95f));
    int d = (int)__fmul_rn(64.0f, __fadd_rn(0.5f, __fmul_rn(0.5f, bw)));
    d = min(max(d, 1), 480);            // effectively [33, 63]

    float inv_att;
    asm("rcp.approx.f32 %0, %1;" : "=f"(inv_att) : "f"(att));
    const float a2 = -LOG2E * inv_att;  // env(i) = ex2(i*a2)

    float r, e0, e32, etap;
    asm("ex2.approx.f32 %0, %1;" : "=f"(r)    : "f"(a2));
    asm("ex2.approx.f32 %0, %1;" : "=f"(e0)   : "f"((float)i0 * a2));
    asm("ex2.approx.f32 %0, %1;" : "=f"(e32)  : "f"(32.0f * a2));
    asm("ex2.approx.f32 %0, %1;" : "=f"(etap) : "f"(-(float)d * a2));
    e0 *= energy;
    const float e1 = e0 * r, e2 = e1 * r, e3 = e2 * r;
    const float tf = tilt * etap;       // <= |tilt|*e^7.9, no overflow

    // lo chunk: elements i0..i0+3 <= 31 < 33 <= d  =>  never tapped.
    y[0] = e0 * nlo.x;
    y[1] = e1 * nlo.y;
    y[2] = e2 * nlo.z;
    y[3] = e3 * nlo.w;

    // hi chunk: element i = i0+32+k, tap j = i-d in [-31, 30]. L1 hits.
    const int    jb = i0 + 32 - d;
    const float* np = noise + (row * 64 + jb);
    const float m0 = (jb + 0 >= 0) ? np[0] : 0.0f;
    const float m1 = (jb + 1 >= 0) ? np[1] : 0.0f;
    const float m2 = (jb + 2 >= 0) ? np[2] : 0.0f;
    const float m3 = (jb + 3 >= 0) ? np[3] : 0.0f;

    z[0] = (e0 * e32) * __fmaf_rn(tf, m0, nhi.x);
    z[1] = (e1 * e32) * __fmaf_rn(tf, m1, nhi.y);
    z[2] = (e2 * e32) * __fmaf_rn(tf, m2, nhi.z);
    z[3] = (e3 * e32) * __fmaf_rn(tf, m3, nhi.w);

    ss = (y[0] * y[0] + y[1] * y[1] + y[2] * y[2] + y[3] * y[3])
       + (z[0] * z[0] + z[1] * z[1] + z[2] * z[2] + z[3] * z[3]);
}

__global__ __launch_bounds__(256, 6) void tcn_kernel(
    const float4* __restrict__ params,  // [N_ROWS] float4
    const float*  __restrict__ noise,   // [N_ROWS, 64]
    float*        __restrict__ out)     // [N_ROWS, 64]
{
    const int tid  = blockIdx.x * 256 + threadIdx.x;
    const int rowA = tid >> 3;          // in [0, 32000)
    const int rowB = rowA + HALF;
    const int l    = tid & 7;
    const int i0   = l << 2;

    const int baseA = rowA * 64 + i0;
    const int baseB = rowB * 64 + i0;

    // Front-batched loads, params first (longest dependency chain). MLP = 6.
    const float4 pA   = __ldg(params + rowA);
    const float4 pB   = __ldg(params + rowB);
    const float4 nloA = *reinterpret_cast<const float4*>(noise + baseA);
    const float4 nhiA = *reinterpret_cast<const float4*>(noise + baseA + 32);
    const float4 nloB = *reinterpret_cast<const float4*>(noise + baseB);
    const float4 nhiB = *reinterpret_cast<const float4*>(noise + baseB + 32);

    float yA[4], zA[4], yB[4], zB[4], ssA, ssB;
    row_split(pA, nloA, nhiA, noise, rowA, i0, yA, zA, ssA);
    row_split(pB, nloB, nhiB, noise, rowB, i0, yB, zB, ssB);

    // Two independent 8-lane reductions, interleaved (3 butterfly steps).
    #pragma unroll
    for (int o = 4; o > 0; o >>= 1) {
        ssA += __shfl_xor_sync(0xFFFFFFFFu, ssA, o);
        ssB += __shfl_xor_sync(0xFFFFFFFFu, ssB, o);
    }

    const float irA = rsqrtf(ssA * (1.0f / 64.0f) + 1e-5f);
    const float irB = rsqrtf(ssB * (1.0f / 64.0f) + 1e-5f);

    float4 v;
    v.x = yA[0] * irA; v.y = yA[1] * irA; v.z = yA[2] * irA; v.w = yA[3] * irA;
    *reinterpret_cast<float4*>(out + baseA) = v;
    v.x = zA[0] * irA; v.y = zA[1] * irA; v.z = zA[2] * irA; v.w = zA[3] * irA;
    *reinterpret_cast<float4*>(out + baseA + 32) = v;
    v.x = yB[0] * irB; v.y = yB[1] * irB; v.z = yB[2] * irB; v.w = yB[3] * irB;
    *reinterpret_cast<float4*>(out + baseB) = v;
    v.x = zB[0] * irB; v.y = zB[1] * irB; v.z = zB[2] * irB; v.w = zB[3] * irB;
    *reinterpret_cast<float4*>(out + baseB + 32) = v;
}

extern "C" void kernel_launch(void* const* d_in, const int* in_sizes, int n_in,
                              void* d_out, int out_size)
{
    const float4* params = (const float4*)d_in[0];  // [32,2000,4]
    const float*  noise  = (const float*)d_in[1];   // [32,2000,64]
    float* out = (float*)d_out;                     // [32, 2000*64]

    // 32000 row-pairs * 8 lanes / 256 threads = 1000 blocks (exact).
    tcn_kernel<<<(HALF * 8) / 256, 256>>>(params, noise, out);
}

// round 17
// speedup vs baseline: 1.2399x; 1.2399x over previous
#include <cuda_runtime.h>
#include <cuda_bf16.h>

// TransientCombNoise: B=32, T=2000, BLOCK=64, MAX_DELAY=480, SR=16000.
// Per row r of N=64000, params (p0..p3) in [0,1):
//   att   = 16000*(0.0005 + p0*0.0495)            in [8, 800) -> clip dead
//   energy= p1 ; tilt = 2*p2 - 1
//   delay = int(64*(0.5 + 0.5*(0.05 + 0.95*p3)))  in [33, 63] -> clamp dead
//   y[i]  = env(i)*energy*( n[i] + tilt*exp(delay/att)*n[i-delay] )
//   out   = y * rsqrt(mean(y^2) + 1e-5)
//
// R14 winning config (8 lanes/row, split chunks, 16000 warps) + dead-op
// removal + rsqrt.approx. Lane owns elements [4l,4l+3] (lo, NEVER tapped since
// delay >= 33) and [4l+32,4l+35] (hi, the only tapped chunk; taps are L1 hits
// into the row's own 256B line).

#define N_ROWS 64000
#define LOG2E  1.4426950408889634f

__global__ __launch_bounds__(256) void tcn_kernel(
    const float4* __restrict__ params,  // [N_ROWS] float4
    const float*  __restrict__ noise,   // [N_ROWS, 64]
    float*        __restrict__ out)     // [N_ROWS, 64]
{
    const int tid = blockIdx.x * 256 + threadIdx.x;
    const int row = tid >> 3;           // 8 lanes per row
    const int l   = tid & 7;
    const int i0  = l << 2;             // lo chunk start: 0..28

    const int base = row * 64 + i0;     // < 4.1M, fits int

    // Front-batched loads (params head the longest dep chain). MLP = 3.
    const float4 p   = __ldg(params + row);
    const float4 nlo = *reinterpret_cast<const float4*>(noise + base);
    const float4 nhi = *reinterpret_cast<const float4*>(noise + base + 32);

    // Strict-rounded chain so the truncated delay matches JAX fp32 exactly.
    // att >= 8 always (p0 >= 0) -> no clip needed.
    const float att    = __fmul_rn(16000.0f,
                         __fadd_rn(0.0005f, __fmul_rn(p.x, 0.0495f)));
    const float energy = p.y;
    const float tilt   = __fmaf_rn(p.z, 2.0f, -1.0f);
    const float bw     = __fadd_rn(0.05f, __fmul_rn(p.w, 0.95f));
    // d in [33, 63] always (p3 in [0,1)) -> no clamp needed.
    const int d = (int)__fmul_rn(64.0f, __fadd_rn(0.5f, __fmul_rn(0.5f, bw)));

    float inv_att;
    asm("rcp.approx.f32 %0, %1;" : "=f"(inv_att) : "f"(att));
    const float a2 = -LOG2E * inv_att;  // env(i) = ex2(i*a2)

    float r, e0, e32, etap;
    asm("ex2.approx.f32 %0, %1;" : "=f"(r)    : "f"(a2));
    asm("ex2.approx.f32 %0, %1;" : "=f"(e0)   : "f"((float)i0 * a2));
    asm("ex2.approx.f32 %0, %1;" : "=f"(e32)  : "f"(32.0f * a2));
    asm("ex2.approx.f32 %0, %1;" : "=f"(etap) : "f"(-(float)d * a2));
    e0 *= energy;
    const float e1 = e0 * r, e2 = e1 * r, e3 = e2 * r;
    const float tf = tilt * etap;       // <= |tilt|*e^7.9, no overflow

    // lo chunk: elements i0..i0+3 <= 31 < 33 <= d  =>  never tapped.
    const float y0 = e0 * nlo.x;
    const float y1 = e1 * nlo.y;
    const float y2 = e2 * nlo.z;
    const float y3 = e3 * nlo.w;

    // hi chunk: element i = i0+32+k, tap j = i-d in [-31, 30]. L1 hits.
    const int    jb = i0 + 32 - d;
    const float* np = noise + (row * 64 + jb);
    const float m0 = (jb + 0 >= 0) ? np[0] : 0.0f;
    const float m1 = (jb + 1 >= 0) ? np[1] : 0.0f;
    const float m2 = (jb + 2 >= 0) ? np[2] : 0.0f;
    const float m3 = (jb + 3 >= 0) ? np[3] : 0.0f;

    const float z0 = (e0 * e32) * __fmaf_rn(tf, m0, nhi.x);
    const float z1 = (e1 * e32) * __fmaf_rn(tf, m1, nhi.y);
    const float z2 = (e2 * e32) * __fmaf_rn(tf, m2, nhi.z);
    const float z3 = (e3 * e32) * __fmaf_rn(tf, m3, nhi.w);

    // Sum of squares across the 8-lane row group (3-step butterfly).
    float ss = (y0 * y0 + y1 * y1 + y2 * y2 + y3 * y3)
             + (z0 * z0 + z1 * z1 + z2 * z2 + z3 * z3);
    ss += __shfl_xor_sync(0xFFFFFFFFu, ss, 4);
    ss += __shfl_xor_sync(0xFFFFFFFFu, ss, 2);
    ss += __shfl_xor_sync(0xFFFFFFFFu, ss, 1);

    // 1/rms via single MUFU (no refine).
    float ir;
    const float msq = __fmaf_rn(ss, 1.0f / 64.0f, 1e-5f);
    asm("rsqrt.approx.f32 %0, %1;" : "=f"(ir) : "f"(msq));

    float4 olo, ohi;
    olo.x = y0 * ir;  olo.y = y1 * ir;  olo.z = y2 * ir;  olo.w = y3 * ir;
    ohi.x = z0 * ir;  ohi.y = z1 * ir;  ohi.z = z2 * ir;  ohi.w = z3 * ir;
    *reinterpret_cast<float4*>(out + base)      = olo;
    *reinterpret_cast<float4*>(out + base + 32) = ohi;
}

extern "C" void kernel_launch(void* const* d_in, const int* in_sizes, int n_in,
                              void* d_out, int out_size)
{
    const float4* params = (const float4*)d_in[0];  // [32,2000,4]
    const float*  noise  = (const float*)d_in[1];   // [32,2000,64]
    float* out = (float*)d_out;                     // [32, 2000*64]

    // 64000 rows * 8 lanes / 256 threads = 2000 blocks (exact).
    tcn_kernel<<<(N_ROWS * 8) / 256, 256>>>(params, noise, out);
}